// round 1
// baseline (speedup 1.0000x reference)
#include <cuda_runtime.h>
#include <math.h>

// Problem constants
#define BATCH 64
#define SEG   8
#define CIN   256
#define RNK   64
#define HWSZ  196      // 14*14
#define P1    169      // 13*13
#define M1    10816    // BATCH * P1
#define NB    512      // BNECK == S*R == OUT

// ---------------- scratch (static device globals; no allocations) ----------------
__device__ float g_relu1[BATCH * 512 * P1];   // conv1+relu output  [b][o][p]
__device__ float g_awin[BATCH * 2048];        // window sums A2     [b][c*4+t]
__device__ float g_att_acc[BATCH * 512];      // conv2-mean accumulator
__device__ float g_att[BATCH * 512];          // sigmoid attention  [b][s*64+r]
__device__ int   g_maxidx[BATCH * RNK];       // pivot segment per (b,r)
__device__ float g_total[BATCH * RNK * HWSZ]; // sum_s xr
__device__ float g_pivot[BATCH * RNK * HWSZ]; // xr at pivot segment

// =====================================================================
// Kernel 1: conv1 + bias + relu as implicit GEMM
//   out[m=b*169+p][n=o] = sum_k A[m][k]*B[k][n],  K = 1024 = c*4 + t
//   A gathered on the fly from inputs (2x2 taps), B = att_w1 (layout matches k)
//   Tile 128x128, BK=16, 256 threads, 8x8 per thread.
// =====================================================================
__global__ __launch_bounds__(256, 2)
void k_conv1(const float* __restrict__ in, const float* __restrict__ w1,
             const float* __restrict__ b1)
{
    __shared__ __align__(16) float As[16][128];
    __shared__ __align__(16) float Bs[16][128];

    const int tid   = threadIdx.x;
    const int mt    = blockIdx.x;       // 0..84
    const int nt    = blockIdx.y;       // 0..3
    const int row   = tid & 127;
    const int chalf = tid >> 7;         // 0/1

    const int m  = mt * 128 + row;
    const bool mv = (m < M1);
    const int ms = mv ? m : 0;
    const int b  = ms / 169;
    const int p  = ms % 169;
    const int y  = p / 13, x = p % 13;
    const float* inb = in + (size_t)(b * 8) * CIN * HWSZ + y * 14 + x;

    const int nl = row, kg = chalf;
    const float* w1p = w1 + (size_t)(nt * 128 + nl) * 1024;

    const int tm = tid >> 4;   // 0..15
    const int tn = tid & 15;   // 0..15

    float acc[8][8];
#pragma unroll
    for (int i = 0; i < 8; i++)
#pragma unroll
        for (int j = 0; j < 8; j++) acc[i][j] = 0.f;

    for (int it = 0; it < 64; ++it) {
        // ---- load A tile: each thread fills the 4 taps of 2 input channels
#pragma unroll
        for (int cc = 0; cc < 2; ++cc) {
            const int c = it * 4 + chalf * 2 + cc;
            const float* pA = inb + ((c >> 5) * CIN + (c & 31)) * HWSZ;
            float v0 = 0.f, v1 = 0.f, v2 = 0.f, v3 = 0.f;
            if (mv) { v0 = pA[0]; v1 = pA[1]; v2 = pA[14]; v3 = pA[15]; }
            const int kl = (chalf * 2 + cc) * 4;
            As[kl + 0][row] = v0; As[kl + 1][row] = v1;
            As[kl + 2][row] = v2; As[kl + 3][row] = v3;
        }
        // ---- load B tile (w1 is k-contiguous per output channel)
        {
            const float4 bv0 = *(const float4*)(w1p + it * 16 + kg * 8);
            const float4 bv1 = *(const float4*)(w1p + it * 16 + kg * 8 + 4);
            Bs[kg * 8 + 0][nl] = bv0.x; Bs[kg * 8 + 1][nl] = bv0.y;
            Bs[kg * 8 + 2][nl] = bv0.z; Bs[kg * 8 + 3][nl] = bv0.w;
            Bs[kg * 8 + 4][nl] = bv1.x; Bs[kg * 8 + 5][nl] = bv1.y;
            Bs[kg * 8 + 6][nl] = bv1.z; Bs[kg * 8 + 7][nl] = bv1.w;
        }
        __syncthreads();
#pragma unroll
        for (int kk = 0; kk < 16; ++kk) {
            float a[8], bb[8];
            *(float4*)&a[0]  = *(const float4*)&As[kk][tm * 8];
            *(float4*)&a[4]  = *(const float4*)&As[kk][tm * 8 + 4];
            *(float4*)&bb[0] = *(const float4*)&Bs[kk][tn * 8];
            *(float4*)&bb[4] = *(const float4*)&Bs[kk][tn * 8 + 4];
#pragma unroll
            for (int i = 0; i < 8; i++)
#pragma unroll
                for (int j = 0; j < 8; j++)
                    acc[i][j] = fmaf(a[i], bb[j], acc[i][j]);
        }
        __syncthreads();
    }

    // ---- epilogue: bias + relu, store [b][o][p]
#pragma unroll
    for (int i = 0; i < 8; i++) {
        const int mm = mt * 128 + tm * 8 + i;
        if (mm >= M1) continue;
        const int bo = mm / 169, po = mm % 169;
#pragma unroll
        for (int j = 0; j < 8; j++) {
            const int n = nt * 128 + tn * 8 + j;
            float v = acc[i][j] + b1[n];
            g_relu1[(size_t)(bo * 512 + n) * 169 + po] = v > 0.f ? v : 0.f;
        }
    }
}

// =====================================================================
// Kernel 2: per (b,c) row, compute the four 12x12 window sums of relu1.
//           Also zeroes g_att_acc and g_total (stream-ordered before use).
//   One warp per row; predicate masks select each window.
// =====================================================================
__global__ __launch_bounds__(256)
void k_win()
{
    const int gtid = blockIdx.x * 256 + threadIdx.x;
    if (gtid < BATCH * 512)        g_att_acc[gtid] = 0.f;
    if (gtid < BATCH * RNK * HWSZ) g_total[gtid]   = 0.f;

    const int wid = gtid >> 5, lane = gtid & 31;
    if (wid >= BATCH * 512) return;
    const float* rowp = g_relu1 + (size_t)wid * 169;

    float w00 = 0.f, w01 = 0.f, w10 = 0.f, w11 = 0.f;
    for (int i = lane; i < 169; i += 32) {
        const float v = rowp[i];
        const int y = (i * 79) >> 10;   // i/13 for i<=168
        const int x = i - y * 13;
        if (y < 12) { if (x < 12) w00 += v; if (x > 0) w01 += v; }
        if (y > 0)  { if (x < 12) w10 += v; if (x > 0) w11 += v; }
    }
#pragma unroll
    for (int o = 16; o; o >>= 1) {
        w00 += __shfl_down_sync(0xffffffffu, w00, o);
        w01 += __shfl_down_sync(0xffffffffu, w01, o);
        w10 += __shfl_down_sync(0xffffffffu, w10, o);
        w11 += __shfl_down_sync(0xffffffffu, w11, o);
    }
    if (lane == 0)
        *(float4*)&g_awin[wid * 4] = make_float4(w00, w01, w10, w11);
}

// =====================================================================
// Kernel 3: conv2-as-GEMM on window sums. M=64(b), N=512(o), K=2048.
//   K-split across blocks, partial tiles atomically accumulated.
// =====================================================================
__global__ __launch_bounds__(256)
void k_gemm2(const float* __restrict__ w2)
{
    __shared__ __align__(16) float As[16][64];
    __shared__ __align__(16) float Bs[16][64];

    const int ot = blockIdx.x;  // 0..7  (64 output channels each)
    const int ks = blockIdx.y;  // 0..15 (K chunk of 128)
    const int tid = threadIdx.x;
    const int l = tid & 63, kg = tid >> 6;
    const int tm = tid >> 4, tn = tid & 15;

    float acc[4][4];
#pragma unroll
    for (int i = 0; i < 4; i++)
#pragma unroll
        for (int j = 0; j < 4; j++) acc[i][j] = 0.f;

    for (int it = 0; it < 8; ++it) {
        const int kb = ks * 128 + it * 16;
        const float4 av = *(const float4*)&g_awin[l * 2048 + kb + kg * 4];
        const float4 bv = *(const float4*)(w2 + (size_t)(ot * 64 + l) * 2048 + kb + kg * 4);
        As[kg * 4 + 0][l] = av.x; As[kg * 4 + 1][l] = av.y;
        As[kg * 4 + 2][l] = av.z; As[kg * 4 + 3][l] = av.w;
        Bs[kg * 4 + 0][l] = bv.x; Bs[kg * 4 + 1][l] = bv.y;
        Bs[kg * 4 + 2][l] = bv.z; Bs[kg * 4 + 3][l] = bv.w;
        __syncthreads();
#pragma unroll
        for (int kk = 0; kk < 16; ++kk) {
            float a[4], bb[4];
            *(float4*)&a[0]  = *(const float4*)&As[kk][tm * 4];
            *(float4*)&bb[0] = *(const float4*)&Bs[kk][tn * 4];
#pragma unroll
            for (int i = 0; i < 4; i++)
#pragma unroll
                for (int j = 0; j < 4; j++)
                    acc[i][j] = fmaf(a[i], bb[j], acc[i][j]);
        }
        __syncthreads();
    }
#pragma unroll
    for (int i = 0; i < 4; i++)
#pragma unroll
        for (int j = 0; j < 4; j++)
            atomicAdd(&g_att_acc[(tm * 4 + i) * 512 + ot * 64 + tn * 4 + j], acc[i][j]);
}

// =====================================================================
// Kernel 4: mean-scale + bias + sigmoid, argmax over segments (first-max).
// =====================================================================
__global__ void k_att(const float* __restrict__ b2)
{
    const int b = blockIdx.x, r = threadIdx.x;  // 64 x 64
    float best = -1e30f; int bi = 0;
#pragma unroll
    for (int s = 0; s < 8; s++) {
        const float v = g_att_acc[b * 512 + s * 64 + r] * (1.f / 144.f) + b2[s * 64 + r];
        const float a = 1.f / (1.f + expf(-v));
        g_att[b * 512 + s * 64 + r] = a;
        if (a > best) { best = a; bi = s; }
    }
    g_maxidx[b * 64 + r] = bi;
}

// =====================================================================
// Kernel 5: grouped rank projection + attention weighting + segment sum
//           + pivot extraction. Per (hw-tile, s, b) block: 64x64x256 GEMM.
// =====================================================================
__global__ __launch_bounds__(256)
void k_rank(const float* __restrict__ in, const float* __restrict__ rank_w,
            const float* __restrict__ rank_b)
{
    __shared__ __align__(16) float As[16][64];
    __shared__ __align__(16) float Bs[16][64];

    const int ht = blockIdx.x;   // 0..3 (hw tiles of 64)
    const int s  = blockIdx.y;   // 0..7
    const int b  = blockIdx.z;   // 0..63
    const int tid = threadIdx.x;
    const int l = tid & 63, kg = tid >> 6;
    const int hwb = ht * 64;
    const int tm = tid >> 4, tn = tid & 15;

    const float* img = in + (size_t)(b * 8 + s) * CIN * HWSZ;
    const float* wrk = rank_w + (size_t)s * RNK * CIN;

    float acc[4][4];
#pragma unroll
    for (int i = 0; i < 4; i++)
#pragma unroll
        for (int j = 0; j < 4; j++) acc[i][j] = 0.f;

    for (int it = 0; it < 16; ++it) {
        const int kb = it * 16;
        const float4 av = *(const float4*)(wrk + (size_t)l * 256 + kb + kg * 4);
        As[kg * 4 + 0][l] = av.x; As[kg * 4 + 1][l] = av.y;
        As[kg * 4 + 2][l] = av.z; As[kg * 4 + 3][l] = av.w;
        const int hw = hwb + l;
#pragma unroll
        for (int j = 0; j < 4; j++) {
            const int k = kb + kg * 4 + j;
            Bs[kg * 4 + j][l] = (hw < HWSZ) ? img[k * HWSZ + hw] : 0.f;
        }
        __syncthreads();
#pragma unroll
        for (int kk = 0; kk < 16; ++kk) {
            float a[4], bb[4];
            *(float4*)&a[0]  = *(const float4*)&As[kk][tm * 4];
            *(float4*)&bb[0] = *(const float4*)&Bs[kk][tn * 4];
#pragma unroll
            for (int i = 0; i < 4; i++)
#pragma unroll
                for (int j = 0; j < 4; j++)
                    acc[i][j] = fmaf(a[i], bb[j], acc[i][j]);
        }
        __syncthreads();
    }

#pragma unroll
    for (int i = 0; i < 4; i++) {
        const int r = tm * 4 + i;
        const float att = g_att[b * 512 + s * 64 + r];
        const float rb  = rank_b[s * 64 + r];
        const int mi    = g_maxidx[b * 64 + r];
#pragma unroll
        for (int j = 0; j < 4; j++) {
            const int hw = hwb + tn * 4 + j;
            if (hw < HWSZ) {
                const float xr = (acc[i][j] + rb) * att;
                const size_t o = (size_t)(b * 64 + r) * HWSZ + hw;
                atomicAdd(&g_total[o], xr);
                if (mi == s) g_pivot[o] = xr;
            }
        }
    }
}

// =====================================================================
// Kernel 6: y = pivot*(total - pivot)/7, spatial mean, final linear.
// =====================================================================
__global__ __launch_bounds__(256)
void k_final(const float* __restrict__ lin_w, const float* __restrict__ lin_b,
             float* __restrict__ out)
{
    __shared__ float pooled[64];
    const int b = blockIdx.x;
    const int tid = threadIdx.x, wid = tid >> 5, lane = tid & 31;

#pragma unroll
    for (int rr = 0; rr < 8; ++rr) {
        const int r = wid * 8 + rr;
        const float* tp = g_total + (size_t)(b * 64 + r) * HWSZ;
        const float* pp = g_pivot + (size_t)(b * 64 + r) * HWSZ;
        float sum = 0.f;
        for (int i = lane; i < HWSZ; i += 32) {
            const float pv = pp[i];
            sum += pv * (tp[i] - pv);
        }
#pragma unroll
        for (int o = 16; o; o >>= 1) sum += __shfl_down_sync(0xffffffffu, sum, o);
        if (lane == 0) pooled[r] = sum * (1.f / (7.f * 196.f));
    }
    __syncthreads();

#pragma unroll
    for (int oo = 0; oo < 2; ++oo) {
        const int o = oo * 256 + tid;
        float a = lin_b[o];
#pragma unroll
        for (int r = 0; r < 64; r++)
            a = fmaf(pooled[r], lin_w[o * 64 + r], a);
        out[b * 512 + o] = a;
    }
}

// =====================================================================
extern "C" void kernel_launch(void* const* d_in, const int* in_sizes, int n_in,
                              void* d_out, int out_size)
{
    const float* in = (const float*)d_in[0];
    const float* w1 = (const float*)d_in[1];
    const float* b1 = (const float*)d_in[2];
    const float* w2 = (const float*)d_in[3];
    const float* b2 = (const float*)d_in[4];
    const float* rw = (const float*)d_in[5];
    const float* rb = (const float*)d_in[6];
    const float* lw = (const float*)d_in[7];
    const float* lb = (const float*)d_in[8];
    float* out = (float*)d_out;

    k_conv1<<<dim3(85, 4), 256>>>(in, w1, b1);
    k_win  <<<4096, 256>>>();
    k_gemm2<<<dim3(8, 16), 256>>>(w2);
    k_att  <<<64, 64>>>(b2);
    k_rank <<<dim3(4, 8, 64), 256>>>(in, rw, rb);
    k_final<<<64, 256>>>(lw, lb, out);
}

// round 2
// speedup vs baseline: 1.0760x; 1.0760x over previous
#include <cuda_runtime.h>
#include <math.h>
#include <stdint.h>

// Problem constants
#define BATCH 64
#define SEG   8
#define CIN   256
#define RNK   64
#define HWSZ  196      // 14*14
#define P1    169      // 13*13
#define M1    10816    // BATCH * P1
#define NB    512      // BNECK == S*R == OUT

// ---------------- scratch (static device globals; no allocations) ----------------
__device__ float g_relu1[BATCH * 512 * P1];   // conv1+relu output  [b][o][p]
__device__ float g_awin[BATCH * 2048];        // window sums A2     [b][c*4+t]
__device__ float g_att_acc[BATCH * 512];      // conv2-mean accumulator
__device__ float g_att[BATCH * 512];          // sigmoid attention  [b][s*64+r]
__device__ int   g_maxidx[BATCH * RNK];       // pivot segment per (b,r)
__device__ float g_total[BATCH * RNK * HWSZ]; // sum_s xr
__device__ float g_pivot[BATCH * RNK * HWSZ]; // xr at pivot segment

// ---------------- tf32 helpers ----------------
__device__ __forceinline__ float f2tf(float v) {
    uint32_t r;
    asm("cvt.rna.tf32.f32 %0, %1;" : "=r"(r) : "f"(v));
    return __uint_as_float(r);
}

__device__ __forceinline__ void mma_tf32(float* d, const uint32_t* a,
                                         uint32_t b0, uint32_t b1) {
    asm volatile(
        "mma.sync.aligned.m16n8k8.row.col.f32.tf32.tf32.f32 "
        "{%0,%1,%2,%3},{%4,%5,%6,%7},{%8,%9},{%0,%1,%2,%3};"
        : "+f"(d[0]), "+f"(d[1]), "+f"(d[2]), "+f"(d[3])
        : "r"(a[0]), "r"(a[1]), "r"(a[2]), "r"(a[3]), "r"(b0), "r"(b1));
}

// =====================================================================
// Kernel 1: conv1 + bias + relu as implicit GEMM on tensor cores (3xTF32)
//   C[m=b*169+p][n=o] = sum_k A[m][k]*B[k][n],  K = 1024 = c*4 + tap
//   CTA tile 128x128, BK=8, 8 warps of 32x64 (m16n8k8), double-buffered.
// =====================================================================
#define PADW 136   // 8-float pad -> conflict-free frag reads

__global__ __launch_bounds__(256, 1)
void k_conv1(const float* __restrict__ in, const float* __restrict__ w1,
             const float* __restrict__ b1)
{
    __shared__ float As_h[2][8][PADW], As_l[2][8][PADW];
    __shared__ float Bs_h[2][8][PADW], Bs_l[2][8][PADW];

    const int tid = threadIdx.x;
    const int mt  = blockIdx.x;   // 0..84
    const int nt  = blockIdx.y;   // 0..3

    // ---- loader indices
    const int lm = tid & 127;     // A m-row / B n-col within tile
    const int lh = tid >> 7;      // 0/1

    const int m  = mt * 128 + lm;
    const bool mv = (m < M1);
    const int ms = mv ? m : 0;
    const int b  = ms / 169;
    const int p  = ms % 169;
    const int y  = p / 13, x = p % 13;
    const float* inb = in + (size_t)(b * 8) * CIN * HWSZ + y * 14 + x;
    const float* w1p = w1 + (size_t)(nt * 128 + lm) * 1024 + lh * 4;

    // ---- mma indices
    const int w    = tid >> 5;
    const int lane = tid & 31;
    const int wm   = w & 3;        // 0..3 -> 32-row slab
    const int wn   = w >> 2;       // 0..1 -> 64-col slab
    const int gid  = lane >> 2;    // 0..7
    const int tig  = lane & 3;     // 0..3
    const int am   = wm * 32;
    const int bn   = wn * 64;

    float acc[2][8][4];
#pragma unroll
    for (int i = 0; i < 2; i++)
#pragma unroll
        for (int j = 0; j < 8; j++)
#pragma unroll
            for (int c = 0; c < 4; c++) acc[i][j][c] = 0.f;

    float  av[4];
    float4 bv;

#define LOAD_STAGE(IT) do {                                               \
        const int c_ = (IT) * 2 + lh;                                     \
        const float* pA = inb + ((c_ >> 5) * CIN + (c_ & 31)) * HWSZ;     \
        if (mv) { av[0] = pA[0]; av[1] = pA[1];                           \
                  av[2] = pA[14]; av[3] = pA[15]; }                       \
        else    { av[0] = av[1] = av[2] = av[3] = 0.f; }                  \
        bv = *(const float4*)(w1p + (IT) * 8);                            \
    } while (0)

#define STORE_STAGE(BUF) do {                                             \
        float bb[4] = {bv.x, bv.y, bv.z, bv.w};                           \
        _Pragma("unroll")                                                 \
        for (int j_ = 0; j_ < 4; j_++) {                                  \
            const int kl = lh * 4 + j_;                                   \
            float ah_ = f2tf(av[j_]);                                     \
            As_h[BUF][kl][lm] = ah_;                                      \
            As_l[BUF][kl][lm] = f2tf(av[j_] - ah_);                       \
            float bh_ = f2tf(bb[j_]);                                     \
            Bs_h[BUF][kl][lm] = bh_;                                      \
            Bs_l[BUF][kl][lm] = f2tf(bb[j_] - bh_);                       \
        }                                                                 \
    } while (0)

    LOAD_STAGE(0);
    STORE_STAGE(0);
    __syncthreads();

    for (int it = 0; it < 128; ++it) {
        const int cur = it & 1;
        if (it + 1 < 128) LOAD_STAGE(it + 1);

        // ---- A fragments (hi & lo)
        uint32_t ah[2][4], al[2][4];
#pragma unroll
        for (int i = 0; i < 2; i++) {
            const int mb = am + i * 16 + gid;
            ah[i][0] = __float_as_uint(As_h[cur][tig    ][mb    ]);
            ah[i][1] = __float_as_uint(As_h[cur][tig    ][mb + 8]);
            ah[i][2] = __float_as_uint(As_h[cur][tig + 4][mb    ]);
            ah[i][3] = __float_as_uint(As_h[cur][tig + 4][mb + 8]);
            al[i][0] = __float_as_uint(As_l[cur][tig    ][mb    ]);
            al[i][1] = __float_as_uint(As_l[cur][tig    ][mb + 8]);
            al[i][2] = __float_as_uint(As_l[cur][tig + 4][mb    ]);
            al[i][3] = __float_as_uint(As_l[cur][tig + 4][mb + 8]);
        }

#pragma unroll
        for (int j = 0; j < 8; j++) {
            const int nb2 = bn + j * 8 + gid;
            const uint32_t bh0 = __float_as_uint(Bs_h[cur][tig    ][nb2]);
            const uint32_t bh1 = __float_as_uint(Bs_h[cur][tig + 4][nb2]);
            const uint32_t bl0 = __float_as_uint(Bs_l[cur][tig    ][nb2]);
            const uint32_t bl1 = __float_as_uint(Bs_l[cur][tig + 4][nb2]);
#pragma unroll
            for (int i = 0; i < 2; i++) {
                mma_tf32(acc[i][j], al[i], bh0, bh1);   // lo*hi
                mma_tf32(acc[i][j], ah[i], bl0, bl1);   // hi*lo
                mma_tf32(acc[i][j], ah[i], bh0, bh1);   // hi*hi
            }
        }

        if (it + 1 < 128) STORE_STAGE(cur ^ 1);
        __syncthreads();
    }

    // ---- epilogue: bias + relu, store [b][o][p]
#pragma unroll
    for (int j = 0; j < 8; j++) {
        const int n0 = nt * 128 + bn + j * 8 + tig * 2;
        const float bia0 = __ldg(b1 + n0);
        const float bia1 = __ldg(b1 + n0 + 1);
#pragma unroll
        for (int i = 0; i < 2; i++) {
            const int mr0 = mt * 128 + am + i * 16 + gid;
#pragma unroll
            for (int h = 0; h < 2; h++) {
                const int mr = mr0 + h * 8;
                if (mr >= M1) continue;
                const int bo = mr / 169, po = mr % 169;
                float v0 = acc[i][j][h * 2 + 0] + bia0;
                float v1 = acc[i][j][h * 2 + 1] + bia1;
                g_relu1[(size_t)(bo * 512 + n0    ) * 169 + po] = v0 > 0.f ? v0 : 0.f;
                g_relu1[(size_t)(bo * 512 + n0 + 1) * 169 + po] = v1 > 0.f ? v1 : 0.f;
            }
        }
    }
#undef LOAD_STAGE
#undef STORE_STAGE
}

// =====================================================================
// Kernel 2: per (b,c) row, compute the four 12x12 window sums of relu1.
//           Also zeroes g_att_acc and g_total (stream-ordered before use).
// =====================================================================
__global__ __launch_bounds__(256)
void k_win()
{
    const int gtid = blockIdx.x * 256 + threadIdx.x;
    if (gtid < BATCH * 512)        g_att_acc[gtid] = 0.f;
    if (gtid < BATCH * RNK * HWSZ) g_total[gtid]   = 0.f;

    const int wid = gtid >> 5, lane = gtid & 31;
    if (wid >= BATCH * 512) return;
    const float* rowp = g_relu1 + (size_t)wid * 169;

    float w00 = 0.f, w01 = 0.f, w10 = 0.f, w11 = 0.f;
    for (int i = lane; i < 169; i += 32) {
        const float v = rowp[i];
        const int y = (i * 79) >> 10;   // i/13 for i<=168
        const int x = i - y * 13;
        if (y < 12) { if (x < 12) w00 += v; if (x > 0) w01 += v; }
        if (y > 0)  { if (x < 12) w10 += v; if (x > 0) w11 += v; }
    }
#pragma unroll
    for (int o = 16; o; o >>= 1) {
        w00 += __shfl_down_sync(0xffffffffu, w00, o);
        w01 += __shfl_down_sync(0xffffffffu, w01, o);
        w10 += __shfl_down_sync(0xffffffffu, w10, o);
        w11 += __shfl_down_sync(0xffffffffu, w11, o);
    }
    if (lane == 0)
        *(float4*)&g_awin[wid * 4] = make_float4(w00, w01, w10, w11);
}

// =====================================================================
// Kernel 3: conv2-as-GEMM on window sums. M=64(b), N=512(o), K=2048.
// =====================================================================
__global__ __launch_bounds__(256)
void k_gemm2(const float* __restrict__ w2)
{
    __shared__ __align__(16) float As[16][64];
    __shared__ __align__(16) float Bs[16][64];

    const int ot = blockIdx.x;  // 0..7  (64 output channels each)
    const int ks = blockIdx.y;  // 0..15 (K chunk of 128)
    const int tid = threadIdx.x;
    const int l = tid & 63, kg = tid >> 6;
    const int tm = tid >> 4, tn = tid & 15;

    float acc[4][4];
#pragma unroll
    for (int i = 0; i < 4; i++)
#pragma unroll
        for (int j = 0; j < 4; j++) acc[i][j] = 0.f;

    for (int it = 0; it < 8; ++it) {
        const int kb = ks * 128 + it * 16;
        const float4 av = *(const float4*)&g_awin[l * 2048 + kb + kg * 4];
        const float4 bv = *(const float4*)(w2 + (size_t)(ot * 64 + l) * 2048 + kb + kg * 4);
        As[kg * 4 + 0][l] = av.x; As[kg * 4 + 1][l] = av.y;
        As[kg * 4 + 2][l] = av.z; As[kg * 4 + 3][l] = av.w;
        Bs[kg * 4 + 0][l] = bv.x; Bs[kg * 4 + 1][l] = bv.y;
        Bs[kg * 4 + 2][l] = bv.z; Bs[kg * 4 + 3][l] = bv.w;
        __syncthreads();
#pragma unroll
        for (int kk = 0; kk < 16; ++kk) {
            float a[4], bb[4];
            *(float4*)&a[0]  = *(const float4*)&As[kk][tm * 4];
            *(float4*)&bb[0] = *(const float4*)&Bs[kk][tn * 4];
#pragma unroll
            for (int i = 0; i < 4; i++)
#pragma unroll
                for (int j = 0; j < 4; j++)
                    acc[i][j] = fmaf(a[i], bb[j], acc[i][j]);
        }
        __syncthreads();
    }
#pragma unroll
    for (int i = 0; i < 4; i++)
#pragma unroll
        for (int j = 0; j < 4; j++)
            atomicAdd(&g_att_acc[(tm * 4 + i) * 512 + ot * 64 + tn * 4 + j], acc[i][j]);
}

// =====================================================================
// Kernel 4: mean-scale + bias + sigmoid, argmax over segments (first-max).
// =====================================================================
__global__ void k_att(const float* __restrict__ b2)
{
    const int b = blockIdx.x, r = threadIdx.x;  // 64 x 64
    float best = -1e30f; int bi = 0;
#pragma unroll
    for (int s = 0; s < 8; s++) {
        const float v = g_att_acc[b * 512 + s * 64 + r] * (1.f / 144.f) + b2[s * 64 + r];
        const float a = 1.f / (1.f + expf(-v));
        g_att[b * 512 + s * 64 + r] = a;
        if (a > best) { best = a; bi = s; }
    }
    g_maxidx[b * 64 + r] = bi;
}

// =====================================================================
// Kernel 5: grouped rank projection + attention weighting + segment sum
//           + pivot extraction. Per (hw-tile, s, b) block: 64x64x256 GEMM.
// =====================================================================
__global__ __launch_bounds__(256)
void k_rank(const float* __restrict__ in, const float* __restrict__ rank_w,
            const float* __restrict__ rank_b)
{
    __shared__ __align__(16) float As[16][64];
    __shared__ __align__(16) float Bs[16][64];

    const int ht = blockIdx.x;   // 0..3 (hw tiles of 64)
    const int s  = blockIdx.y;   // 0..7
    const int b  = blockIdx.z;   // 0..63
    const int tid = threadIdx.x;
    const int l = tid & 63, kg = tid >> 6;
    const int hwb = ht * 64;
    const int tm = tid >> 4, tn = tid & 15;

    const float* img = in + (size_t)(b * 8 + s) * CIN * HWSZ;
    const float* wrk = rank_w + (size_t)s * RNK * CIN;

    float acc[4][4];
#pragma unroll
    for (int i = 0; i < 4; i++)
#pragma unroll
        for (int j = 0; j < 4; j++) acc[i][j] = 0.f;

    for (int it = 0; it < 16; ++it) {
        const int kb = it * 16;
        const float4 av = *(const float4*)(wrk + (size_t)l * 256 + kb + kg * 4);
        As[kg * 4 + 0][l] = av.x; As[kg * 4 + 1][l] = av.y;
        As[kg * 4 + 2][l] = av.z; As[kg * 4 + 3][l] = av.w;
        const int hw = hwb + l;
#pragma unroll
        for (int j = 0; j < 4; j++) {
            const int k = kb + kg * 4 + j;
            Bs[kg * 4 + j][l] = (hw < HWSZ) ? img[k * HWSZ + hw] : 0.f;
        }
        __syncthreads();
#pragma unroll
        for (int kk = 0; kk < 16; ++kk) {
            float a[4], bb[4];
            *(float4*)&a[0]  = *(const float4*)&As[kk][tm * 4];
            *(float4*)&bb[0] = *(const float4*)&Bs[kk][tn * 4];
#pragma unroll
            for (int i = 0; i < 4; i++)
#pragma unroll
                for (int j = 0; j < 4; j++)
                    acc[i][j] = fmaf(a[i], bb[j], acc[i][j]);
        }
        __syncthreads();
    }

#pragma unroll
    for (int i = 0; i < 4; i++) {
        const int r = tm * 4 + i;
        const float att = g_att[b * 512 + s * 64 + r];
        const float rb  = rank_b[s * 64 + r];
        const int mi    = g_maxidx[b * 64 + r];
#pragma unroll
        for (int j = 0; j < 4; j++) {
            const int hw = hwb + tn * 4 + j;
            if (hw < HWSZ) {
                const float xr = (acc[i][j] + rb) * att;
                const size_t o = (size_t)(b * 64 + r) * HWSZ + hw;
                atomicAdd(&g_total[o], xr);
                if (mi == s) g_pivot[o] = xr;
            }
        }
    }
}

// =====================================================================
// Kernel 6: y = pivot*(total - pivot)/7, spatial mean, final linear.
// =====================================================================
__global__ __launch_bounds__(256)
void k_final(const float* __restrict__ lin_w, const float* __restrict__ lin_b,
             float* __restrict__ out)
{
    __shared__ float pooled[64];
    const int b = blockIdx.x;
    const int tid = threadIdx.x, wid = tid >> 5, lane = tid & 31;

#pragma unroll
    for (int rr = 0; rr < 8; ++rr) {
        const int r = wid * 8 + rr;
        const float* tp = g_total + (size_t)(b * 64 + r) * HWSZ;
        const float* pp = g_pivot + (size_t)(b * 64 + r) * HWSZ;
        float sum = 0.f;
        for (int i = lane; i < HWSZ; i += 32) {
            const float pv = pp[i];
            sum += pv * (tp[i] - pv);
        }
#pragma unroll
        for (int o = 16; o; o >>= 1) sum += __shfl_down_sync(0xffffffffu, sum, o);
        if (lane == 0) pooled[r] = sum * (1.f / (7.f * 196.f));
    }
    __syncthreads();

#pragma unroll
    for (int oo = 0; oo < 2; ++oo) {
        const int o = oo * 256 + tid;
        float a = lin_b[o];
#pragma unroll
        for (int r = 0; r < 64; r++)
            a = fmaf(pooled[r], lin_w[o * 64 + r], a);
        out[b * 512 + o] = a;
    }
}

// =====================================================================
extern "C" void kernel_launch(void* const* d_in, const int* in_sizes, int n_in,
                              void* d_out, int out_size)
{
    const float* in = (const float*)d_in[0];
    const float* w1 = (const float*)d_in[1];
    const float* b1 = (const float*)d_in[2];
    const float* w2 = (const float*)d_in[3];
    const float* b2 = (const float*)d_in[4];
    const float* rw = (const float*)d_in[5];
    const float* rb = (const float*)d_in[6];
    const float* lw = (const float*)d_in[7];
    const float* lb = (const float*)d_in[8];
    float* out = (float*)d_out;

    k_conv1<<<dim3(85, 4), 256>>>(in, w1, b1);
    k_win  <<<4096, 256>>>();
    k_gemm2<<<dim3(8, 16), 256>>>(w2);
    k_att  <<<64, 64>>>(b2);
    k_rank <<<dim3(4, 8, 64), 256>>>(in, rw, rb);
    k_final<<<64, 256>>>(lw, lb, out);
}

// round 4
// speedup vs baseline: 1.5273x; 1.4195x over previous
#include <cuda_runtime.h>
#include <cuda_fp16.h>
#include <math.h>
#include <stdint.h>

// Problem constants
#define BATCH 64
#define SEG   8
#define CIN   256
#define RNK   64
#define HWSZ  196      // 14*14
#define P1    169      // 13*13
#define M1    10816    // BATCH * P1
#define NB    512

// ---------------- scratch ----------------
__device__ float g_relu1[BATCH * 512 * P1];
__device__ float g_awin[BATCH * 2048];
__device__ float g_att_acc[BATCH * 512];
__device__ float g_att[BATCH * 512];
__device__ int   g_maxidx[BATCH * RNK];
__device__ float g_total[BATCH * RNK * HWSZ];
__device__ float g_pivot[BATCH * RNK * HWSZ];

// ---------------- helpers ----------------
__device__ __forceinline__ uint32_t smem_u32(const void* p) {
    uint32_t a;
    asm("{ .reg .u64 t; cvta.to.shared.u64 t, %1; cvt.u32.u64 %0, t; }"
        : "=r"(a) : "l"(p));
    return a;
}

__device__ __forceinline__ void mma_f16(float* d, const uint32_t* a,
                                        uint32_t b0, uint32_t b1) {
    asm volatile(
        "mma.sync.aligned.m16n8k16.row.col.f32.f16.f16.f32 "
        "{%0,%1,%2,%3},{%4,%5,%6,%7},{%8,%9},{%0,%1,%2,%3};"
        : "+f"(d[0]), "+f"(d[1]), "+f"(d[2]), "+f"(d[3])
        : "r"(a[0]), "r"(a[1]), "r"(a[2]), "r"(a[3]), "r"(b0), "r"(b1));
}

__device__ __forceinline__ void ldsm4(uint32_t* r, uint32_t addr) {
    asm volatile("ldmatrix.sync.aligned.m8n8.x4.shared.b16 {%0,%1,%2,%3}, [%4];"
                 : "=r"(r[0]), "=r"(r[1]), "=r"(r[2]), "=r"(r[3]) : "r"(addr));
}

// split fp32 -> (hi, lo) fp16 pair; residual exact in fp32
__device__ __forceinline__ void split2(float v, __half& h, __half& l) {
    h = __float2half_rn(v);
    l = __float2half_rn(v - __half2float(h));
}

// =====================================================================
// Kernel 1: conv1 + bias + relu, fp16x2 3-pass mma.sync implicit GEMM
//   C[m][n] = sum_k A[m][k] B[n][k],  M-tile 128, N-tile 128, K=1024
//   BK=16, 64 stages, double-buffered smem, 48B row stride (conflict-free).
//   8 warps: warp tile 32m x 64n of m16n8k16.
// =====================================================================
#define ASTR 24   // halves per row (48B)

__global__ __launch_bounds__(256)
void k_conv1(const float* __restrict__ in, const float* __restrict__ w1,
             const float* __restrict__ b1)
{
    __shared__ __align__(16) __half sAh[2][128 * ASTR];
    __shared__ __align__(16) __half sAl[2][128 * ASTR];
    __shared__ __align__(16) __half sBh[2][128 * ASTR];
    __shared__ __align__(16) __half sBl[2][128 * ASTR];

    const int tid = threadIdx.x;
    const int mt  = blockIdx.x;   // 0..84
    const int nt  = blockIdx.y;   // 0..3

    // ---- loader indices
    const int lm = tid & 127;     // A m-row / B n-row within tile
    const int lh = tid >> 7;      // k-half: 0 -> k0-7, 1 -> k8-15

    const int m  = mt * 128 + lm;
    const bool mv = (m < M1);
    const int ms = mv ? m : 0;
    const int bb = ms / 169;
    const int p  = ms % 169;
    const int yy = p / 13, xx = p % 13;
    const float* inb = in + (size_t)(bb * 8) * CIN * HWSZ + yy * 14 + xx;
    const float* w1p = w1 + (size_t)(nt * 128 + lm) * 1024;

    // store addresses (halves): row lm, offset lh*8
    const uint32_t stAh = smem_u32(&sAh[0][lm * ASTR + lh * 8]);
    const uint32_t stAl = smem_u32(&sAl[0][lm * ASTR + lh * 8]);
    const uint32_t stBh = smem_u32(&sBh[0][lm * ASTR + lh * 8]);
    const uint32_t stBl = smem_u32(&sBl[0][lm * ASTR + lh * 8]);
    const uint32_t bufB = 128 * ASTR * 2;  // bytes per buffer plane

    // ---- mma indices
    const int w    = tid >> 5;
    const int lane = tid & 31;
    const int wm   = w & 3;        // m slab (32 rows)
    const int wn   = w >> 2;       // n slab (64 cols)
    const int am   = wm * 32;
    const int bn   = wn * 64;

    // ldmatrix lane addressing
    const int lr  = lane & 7;
    const int sel = lane >> 3;
    // A: matrices {m0-7,k0},{m8-15,k0},{m0-7,k8},{m8-15,k8}
    const int aRow  = (sel & 1) * 8 + lr;
    const int aByte = (sel >> 1) * 16;
    // B: matrices {n0-7,k0},{n0-7,k8},{n8-15,k0},{n8-15,k8}
    const int bRow  = (sel >> 1) * 8 + lr;
    const int bByte = (sel & 1) * 16;

    const uint32_t baseAh = smem_u32(&sAh[0][0]);
    const uint32_t baseAl = smem_u32(&sAl[0][0]);
    const uint32_t baseBh = smem_u32(&sBh[0][0]);
    const uint32_t baseBl = smem_u32(&sBl[0][0]);

    float acc[2][8][4];
#pragma unroll
    for (int i = 0; i < 2; i++)
#pragma unroll
        for (int j = 0; j < 8; j++)
#pragma unroll
            for (int c = 0; c < 4; c++) acc[i][j][c] = 0.f;

    float av[8];    // A staging: 2 channels x 4 taps
    float bv[8];    // B staging: 8 k-values

#define LOAD_REGS(ST) do {                                                \
        _Pragma("unroll")                                                 \
        for (int cc = 0; cc < 2; ++cc) {                                  \
            const int ch = (ST) * 4 + lh * 2 + cc;                        \
            const float* pA = inb + ((ch >> 5) * CIN + (ch & 31)) * HWSZ; \
            if (mv) { av[cc*4+0] = pA[0];  av[cc*4+1] = pA[1];            \
                      av[cc*4+2] = pA[14]; av[cc*4+3] = pA[15]; }         \
            else    { av[cc*4+0]=av[cc*4+1]=av[cc*4+2]=av[cc*4+3]=0.f; }  \
        }                                                                 \
        const float4 v0 = *(const float4*)(w1p + (ST) * 16 + lh * 8);     \
        const float4 v1 = *(const float4*)(w1p + (ST) * 16 + lh * 8 + 4); \
        bv[0]=v0.x; bv[1]=v0.y; bv[2]=v0.z; bv[3]=v0.w;                   \
        bv[4]=v1.x; bv[5]=v1.y; bv[6]=v1.z; bv[7]=v1.w;                   \
    } while (0)

#define STORE_REGS(BUF) do {                                              \
        __half h[8], l[8];                                                \
        _Pragma("unroll")                                                 \
        for (int q = 0; q < 8; ++q) split2(av[q], h[q], l[q]);            \
        asm volatile("st.shared.v4.b32 [%0], {%1,%2,%3,%4};" ::           \
            "r"(stAh + (BUF) * bufB),                                     \
            "r"(*(const uint32_t*)&h[0]), "r"(*(const uint32_t*)&h[2]),   \
            "r"(*(const uint32_t*)&h[4]), "r"(*(const uint32_t*)&h[6]));  \
        asm volatile("st.shared.v4.b32 [%0], {%1,%2,%3,%4};" ::           \
            "r"(stAl + (BUF) * bufB),                                     \
            "r"(*(const uint32_t*)&l[0]), "r"(*(const uint32_t*)&l[2]),   \
            "r"(*(const uint32_t*)&l[4]), "r"(*(const uint32_t*)&l[6]));  \
        _Pragma("unroll")                                                 \
        for (int q = 0; q < 8; ++q) split2(bv[q], h[q], l[q]);            \
        asm volatile("st.shared.v4.b32 [%0], {%1,%2,%3,%4};" ::           \
            "r"(stBh + (BUF) * bufB),                                     \
            "r"(*(const uint32_t*)&h[0]), "r"(*(const uint32_t*)&h[2]),   \
            "r"(*(const uint32_t*)&h[4]), "r"(*(const uint32_t*)&h[6]));  \
        asm volatile("st.shared.v4.b32 [%0], {%1,%2,%3,%4};" ::           \
            "r"(stBl + (BUF) * bufB),                                     \
            "r"(*(const uint32_t*)&l[0]), "r"(*(const uint32_t*)&l[2]),   \
            "r"(*(const uint32_t*)&l[4]), "r"(*(const uint32_t*)&l[6]));  \
    } while (0)

    LOAD_REGS(0);
    STORE_REGS(0);
    __syncthreads();

    for (int st = 0; st < 64; ++st) {
        const int cur = st & 1;
        if (st + 1 < 64) LOAD_REGS(st + 1);

        // ---- A fragments (hi & lo) for the 2 m16 tiles
        uint32_t ah[2][4], al[2][4];
#pragma unroll
        for (int i = 0; i < 2; i++) {
            const uint32_t ro = (uint32_t)((am + i * 16 + aRow) * ASTR) * 2u + aByte;
            ldsm4(ah[i], baseAh + cur * bufB + ro);
            ldsm4(al[i], baseAl + cur * bufB + ro);
        }

        // ---- B: 4 ldmatrix pairs, each covers 2 n8 tiles; 3-pass mma
#pragma unroll
        for (int jj = 0; jj < 4; ++jj) {
            const uint32_t ro = (uint32_t)((bn + jj * 16 + bRow) * ASTR) * 2u + bByte;
            uint32_t bh[4], bl[4];
            ldsm4(bh, baseBh + cur * bufB + ro);
            ldsm4(bl, baseBl + cur * bufB + ro);
#pragma unroll
            for (int t = 0; t < 2; ++t) {
                const int j = jj * 2 + t;
#pragma unroll
                for (int i = 0; i < 2; ++i) {
                    mma_f16(acc[i][j], ah[i], bh[t * 2], bh[t * 2 + 1]);  // hh
                    mma_f16(acc[i][j], ah[i], bl[t * 2], bl[t * 2 + 1]);  // hl
                    mma_f16(acc[i][j], al[i], bh[t * 2], bh[t * 2 + 1]);  // lh
                }
            }
        }

        if (st + 1 < 64) STORE_REGS(cur ^ 1);
        __syncthreads();
    }

    // ---- epilogue: bias + relu, store [b][o][p]
    const int qr = lane >> 2;   // 0..7
    const int qc = lane & 3;    // 0..3
#pragma unroll
    for (int j = 0; j < 8; j++) {
        const int n0 = nt * 128 + bn + j * 8 + qc * 2;
        const float bia0 = __ldg(b1 + n0);
        const float bia1 = __ldg(b1 + n0 + 1);
#pragma unroll
        for (int i = 0; i < 2; i++) {
            const int m0 = mt * 128 + am + i * 16 + qr;
#pragma unroll
            for (int h = 0; h < 2; h++) {
                const int mr = m0 + h * 8;
                if (mr >= M1) continue;
                const int bo = mr / 169, po = mr % 169;
                float v0 = acc[i][j][h * 2 + 0] + bia0;
                float v1 = acc[i][j][h * 2 + 1] + bia1;
                g_relu1[(size_t)(bo * 512 + n0    ) * 169 + po] = v0 > 0.f ? v0 : 0.f;
                g_relu1[(size_t)(bo * 512 + n0 + 1) * 169 + po] = v1 > 0.f ? v1 : 0.f;
            }
        }
    }
#undef LOAD_REGS
#undef STORE_REGS
}

// =====================================================================
// Zero kernels (run first; also shifts ncu capture slot onto k_conv1)
// =====================================================================
__global__ void k_zero1() {
    const int i = blockIdx.x * 256 + threadIdx.x;
    if (i < BATCH * 512) g_att_acc[i] = 0.f;
}
__global__ void k_zero2() {
    const int i = blockIdx.x * 256 + threadIdx.x;
    if (i < BATCH * RNK * HWSZ / 2) g_total[i] = 0.f;
}
__global__ void k_zero3() {
    const int i = BATCH * RNK * HWSZ / 2 + blockIdx.x * 256 + threadIdx.x;
    if (i < BATCH * RNK * HWSZ) g_total[i] = 0.f;
}

// =====================================================================
// Kernel 2: four 12x12 window sums of relu1 per (b,c) row.
// =====================================================================
__global__ __launch_bounds__(256)
void k_win()
{
    const int gtid = blockIdx.x * 256 + threadIdx.x;
    const int wid = gtid >> 5, lane = gtid & 31;
    if (wid >= BATCH * 512) return;
    const float* rowp = g_relu1 + (size_t)wid * 169;

    float w00 = 0.f, w01 = 0.f, w10 = 0.f, w11 = 0.f;
    for (int i = lane; i < 169; i += 32) {
        const float v = rowp[i];
        const int y = (i * 79) >> 10;
        const int x = i - y * 13;
        if (y < 12) { if (x < 12) w00 += v; if (x > 0) w01 += v; }
        if (y > 0)  { if (x < 12) w10 += v; if (x > 0) w11 += v; }
    }
#pragma unroll
    for (int o = 16; o; o >>= 1) {
        w00 += __shfl_down_sync(0xffffffffu, w00, o);
        w01 += __shfl_down_sync(0xffffffffu, w01, o);
        w10 += __shfl_down_sync(0xffffffffu, w10, o);
        w11 += __shfl_down_sync(0xffffffffu, w11, o);
    }
    if (lane == 0)
        *(float4*)&g_awin[wid * 4] = make_float4(w00, w01, w10, w11);
}

// =====================================================================
// Kernel 3: conv2-as-GEMM on window sums. M=64, N=512, K=2048.
// =====================================================================
__global__ __launch_bounds__(256)
void k_gemm2(const float* __restrict__ w2)
{
    __shared__ __align__(16) float As[16][64];
    __shared__ __align__(16) float Bs[16][64];

    const int ot = blockIdx.x, ks = blockIdx.y;
    const int tid = threadIdx.x;
    const int l = tid & 63, kg = tid >> 6;
    const int tm = tid >> 4, tn = tid & 15;

    float acc[4][4];
#pragma unroll
    for (int i = 0; i < 4; i++)
#pragma unroll
        for (int j = 0; j < 4; j++) acc[i][j] = 0.f;

    for (int it = 0; it < 8; ++it) {
        const int kb = ks * 128 + it * 16;
        const float4 av = *(const float4*)&g_awin[l * 2048 + kb + kg * 4];
        const float4 bv = *(const float4*)(w2 + (size_t)(ot * 64 + l) * 2048 + kb + kg * 4);
        As[kg * 4 + 0][l] = av.x; As[kg * 4 + 1][l] = av.y;
        As[kg * 4 + 2][l] = av.z; As[kg * 4 + 3][l] = av.w;
        Bs[kg * 4 + 0][l] = bv.x; Bs[kg * 4 + 1][l] = bv.y;
        Bs[kg * 4 + 2][l] = bv.z; Bs[kg * 4 + 3][l] = bv.w;
        __syncthreads();
#pragma unroll
        for (int kk = 0; kk < 16; ++kk) {
            float a[4], bbx[4];
            *(float4*)&a[0]   = *(const float4*)&As[kk][tm * 4];
            *(float4*)&bbx[0] = *(const float4*)&Bs[kk][tn * 4];
#pragma unroll
            for (int i = 0; i < 4; i++)
#pragma unroll
                for (int j = 0; j < 4; j++)
                    acc[i][j] = fmaf(a[i], bbx[j], acc[i][j]);
        }
        __syncthreads();
    }
#pragma unroll
    for (int i = 0; i < 4; i++)
#pragma unroll
        for (int j = 0; j < 4; j++)
            atomicAdd(&g_att_acc[(tm * 4 + i) * 512 + ot * 64 + tn * 4 + j], acc[i][j]);
}

// =====================================================================
// Kernel 4: sigmoid attention + argmax.
// =====================================================================
__global__ void k_att(const float* __restrict__ b2)
{
    const int b = blockIdx.x, r = threadIdx.x;
    float best = -1e30f; int bi = 0;
#pragma unroll
    for (int s = 0; s < 8; s++) {
        const float v = g_att_acc[b * 512 + s * 64 + r] * (1.f / 144.f) + b2[s * 64 + r];
        const float a = 1.f / (1.f + expf(-v));
        g_att[b * 512 + s * 64 + r] = a;
        if (a > best) { best = a; bi = s; }
    }
    g_maxidx[b * 64 + r] = bi;
}

// =====================================================================
// Kernel 5: grouped rank projection + att weighting + segment sum + pivot.
// =====================================================================
__global__ __launch_bounds__(256)
void k_rank(const float* __restrict__ in, const float* __restrict__ rank_w,
            const float* __restrict__ rank_b)
{
    __shared__ __align__(16) float As[16][64];
    __shared__ __align__(16) float Bs[16][64];

    const int ht = blockIdx.x, s = blockIdx.y, b = blockIdx.z;
    const int tid = threadIdx.x;
    const int l = tid & 63, kg = tid >> 6;
    const int hwb = ht * 64;
    const int tm = tid >> 4, tn = tid & 15;

    const float* img = in + (size_t)(b * 8 + s) * CIN * HWSZ;
    const float* wrk = rank_w + (size_t)s * RNK * CIN;

    float acc[4][4];
#pragma unroll
    for (int i = 0; i < 4; i++)
#pragma unroll
        for (int j = 0; j < 4; j++) acc[i][j] = 0.f;

    for (int it = 0; it < 16; ++it) {
        const int kb = it * 16;
        const float4 av = *(const float4*)(wrk + (size_t)l * 256 + kb + kg * 4);
        As[kg * 4 + 0][l] = av.x; As[kg * 4 + 1][l] = av.y;
        As[kg * 4 + 2][l] = av.z; As[kg * 4 + 3][l] = av.w;
        const int hw = hwb + l;
#pragma unroll
        for (int j = 0; j < 4; j++) {
            const int k = kb + kg * 4 + j;
            Bs[kg * 4 + j][l] = (hw < HWSZ) ? img[k * HWSZ + hw] : 0.f;
        }
        __syncthreads();
#pragma unroll
        for (int kk = 0; kk < 16; ++kk) {
            float a[4], bbx[4];
            *(float4*)&a[0]   = *(const float4*)&As[kk][tm * 4];
            *(float4*)&bbx[0] = *(const float4*)&Bs[kk][tn * 4];
#pragma unroll
            for (int i = 0; i < 4; i++)
#pragma unroll
                for (int j = 0; j < 4; j++)
                    acc[i][j] = fmaf(a[i], bbx[j], acc[i][j]);
        }
        __syncthreads();
    }

#pragma unroll
    for (int i = 0; i < 4; i++) {
        const int r = tm * 4 + i;
        const float att = g_att[b * 512 + s * 64 + r];
        const float rb  = rank_b[s * 64 + r];
        const int mi    = g_maxidx[b * 64 + r];
#pragma unroll
        for (int j = 0; j < 4; j++) {
            const int hw = hwb + tn * 4 + j;
            if (hw < HWSZ) {
                const float xr = (acc[i][j] + rb) * att;
                const size_t o = (size_t)(b * 64 + r) * HWSZ + hw;
                atomicAdd(&g_total[o], xr);
                if (mi == s) g_pivot[o] = xr;
            }
        }
    }
}

// =====================================================================
// Kernel 6: y = pivot*(total - pivot)/7, spatial mean, final linear.
// =====================================================================
__global__ __launch_bounds__(256)
void k_final(const float* __restrict__ lin_w, const float* __restrict__ lin_b,
             float* __restrict__ out)
{
    __shared__ float pooled[64];
    const int b = blockIdx.x;
    const int tid = threadIdx.x, wid = tid >> 5, lane = tid & 31;

#pragma unroll
    for (int rr = 0; rr < 8; ++rr) {
        const int r = wid * 8 + rr;
        const float* tp = g_total + (size_t)(b * 64 + r) * HWSZ;
        const float* pp = g_pivot + (size_t)(b * 64 + r) * HWSZ;
        float sum = 0.f;
        for (int i = lane; i < HWSZ; i += 32) {
            const float pv = pp[i];
            sum += pv * (tp[i] - pv);
        }
#pragma unroll
        for (int o = 16; o; o >>= 1) sum += __shfl_down_sync(0xffffffffu, sum, o);
        if (lane == 0) pooled[r] = sum * (1.f / (7.f * 196.f));
    }
    __syncthreads();

#pragma unroll
    for (int oo = 0; oo < 2; ++oo) {
        const int o = oo * 256 + tid;
        float a = lin_b[o];
#pragma unroll
        for (int r = 0; r < 64; r++)
            a = fmaf(pooled[r], lin_w[o * 64 + r], a);
        out[b * 512 + o] = a;
    }
}

// =====================================================================
extern "C" void kernel_launch(void* const* d_in, const int* in_sizes, int n_in,
                              void* d_out, int out_size)
{
    const float* in = (const float*)d_in[0];
    const float* w1 = (const float*)d_in[1];
    const float* b1 = (const float*)d_in[2];
    const float* w2 = (const float*)d_in[3];
    const float* b2 = (const float*)d_in[4];
    const float* rw = (const float*)d_in[5];
    const float* rb = (const float*)d_in[6];
    const float* lw = (const float*)d_in[7];
    const float* lb = (const float*)d_in[8];
    float* out = (float*)d_out;

    k_zero1<<<128, 256>>>();
    k_zero2<<<1568, 256>>>();
    k_zero3<<<1568, 256>>>();
    k_conv1<<<dim3(85, 4), 256>>>(in, w1, b1);   // ncu capture slot
    k_win  <<<4096, 256>>>();
    k_gemm2<<<dim3(8, 16), 256>>>(w2);
    k_att  <<<64, 64>>>(b2);
    k_rank <<<dim3(4, 8, 64), 256>>>(in, rw, rb);
    k_final<<<64, 256>>>(lw, lb, out);
}

// round 5
// speedup vs baseline: 1.7623x; 1.1538x over previous
#include <cuda_runtime.h>
#include <cuda_fp16.h>
#include <math.h>
#include <stdint.h>

// Problem constants
#define BATCH 64
#define SEG   8
#define CIN   256
#define RNK   64
#define HWSZ  196      // 14*14
#define P1    169      // 13*13
#define M1    10816    // BATCH * P1
#define NB    512

// ---------------- scratch ----------------
__device__ float g_awin[BATCH * 2048];            // conv1 window sums  [b][c*4+t]
__device__ float g_att_acc[BATCH * 512];          // conv2-mean accumulator
__device__ float g_att[BATCH * 512];              // sigmoid attention  [b][s*64+r]
__device__ int   g_maxidx[BATCH * RNK];           // pivot segment per (b,r)
__device__ float g_xr[BATCH * RNK * SEG * HWSZ];  // xr  [b][r][s][hw]

// ---------------- helpers ----------------
__device__ __forceinline__ uint32_t smem_u32(const void* p) {
    uint32_t a;
    asm("{ .reg .u64 t; cvta.to.shared.u64 t, %1; cvt.u32.u64 %0, t; }"
        : "=r"(a) : "l"(p));
    return a;
}

__device__ __forceinline__ void mma_f16(float* d, const uint32_t* a,
                                        uint32_t b0, uint32_t b1) {
    asm volatile(
        "mma.sync.aligned.m16n8k16.row.col.f32.f16.f16.f32 "
        "{%0,%1,%2,%3},{%4,%5,%6,%7},{%8,%9},{%0,%1,%2,%3};"
        : "+f"(d[0]), "+f"(d[1]), "+f"(d[2]), "+f"(d[3])
        : "r"(a[0]), "r"(a[1]), "r"(a[2]), "r"(a[3]), "r"(b0), "r"(b1));
}

__device__ __forceinline__ void ldsm4(uint32_t* r, uint32_t addr) {
    asm volatile("ldmatrix.sync.aligned.m8n8.x4.shared.b16 {%0,%1,%2,%3}, [%4];"
                 : "=r"(r[0]), "=r"(r[1]), "=r"(r[2]), "=r"(r[3]) : "r"(addr));
}
__device__ __forceinline__ void ldsm4t(uint32_t* r, uint32_t addr) {
    asm volatile("ldmatrix.sync.aligned.m8n8.x4.trans.shared.b16 {%0,%1,%2,%3}, [%4];"
                 : "=r"(r[0]), "=r"(r[1]), "=r"(r[2]), "=r"(r[3]) : "r"(addr));
}

// split fp32 -> (hi, lo) fp16 pair
__device__ __forceinline__ void split2(float v, __half& h, __half& l) {
    h = __float2half_rn(v);
    l = __float2half_rn(v - __half2float(h));
}

// =====================================================================
// Kernel 1: conv1 + bias + relu + FUSED window sums, fp16 3-pass mma
//   C[m][n] = sum_k A[m][k] B[n][k],  M-tile 128, N-tile 128, K=1024
//   Epilogue reduces relu output into the four 12x12 window sums and
//   atomically accumulates g_awin — g_relu1 never materialized.
// =====================================================================
#define ASTR 24   // halves per row (48B)

__global__ __launch_bounds__(256)
void k_conv1(const float* __restrict__ in, const float* __restrict__ w1,
             const float* __restrict__ b1)
{
    __shared__ __align__(16) __half sAh[2][128 * ASTR];
    __shared__ __align__(16) __half sAl[2][128 * ASTR];
    __shared__ __align__(16) __half sBh[2][128 * ASTR];
    __shared__ __align__(16) __half sBl[2][128 * ASTR];

    const int tid = threadIdx.x;
    const int mt  = blockIdx.x;   // 0..84
    const int nt  = blockIdx.y;   // 0..3

    const int lm = tid & 127;
    const int lh = tid >> 7;

    const int m  = mt * 128 + lm;
    const bool mv = (m < M1);
    const int ms = mv ? m : 0;
    const int bb = ms / 169;
    const int p  = ms % 169;
    const int yy = p / 13, xx = p % 13;
    const float* inb = in + (size_t)(bb * 8) * CIN * HWSZ + yy * 14 + xx;
    const float* w1p = w1 + (size_t)(nt * 128 + lm) * 1024;

    const uint32_t stAh = smem_u32(&sAh[0][lm * ASTR + lh * 8]);
    const uint32_t stAl = smem_u32(&sAl[0][lm * ASTR + lh * 8]);
    const uint32_t stBh = smem_u32(&sBh[0][lm * ASTR + lh * 8]);
    const uint32_t stBl = smem_u32(&sBl[0][lm * ASTR + lh * 8]);
    const uint32_t bufB = 128 * ASTR * 2;

    const int w    = tid >> 5;
    const int lane = tid & 31;
    const int wm   = w & 3;
    const int wn   = w >> 2;
    const int am   = wm * 32;
    const int bn   = wn * 64;

    const int lr  = lane & 7;
    const int sel = lane >> 3;
    const int aRow  = (sel & 1) * 8 + lr;
    const int aByte = (sel >> 1) * 16;
    const int bRow  = (sel >> 1) * 8 + lr;
    const int bByte = (sel & 1) * 16;

    const uint32_t baseAh = smem_u32(&sAh[0][0]);
    const uint32_t baseAl = smem_u32(&sAl[0][0]);
    const uint32_t baseBh = smem_u32(&sBh[0][0]);
    const uint32_t baseBl = smem_u32(&sBl[0][0]);

    float acc[2][8][4];
#pragma unroll
    for (int i = 0; i < 2; i++)
#pragma unroll
        for (int j = 0; j < 8; j++)
#pragma unroll
            for (int c = 0; c < 4; c++) acc[i][j][c] = 0.f;

    float av[8];
    float bv[8];

#define LOAD_REGS(ST) do {                                                \
        _Pragma("unroll")                                                 \
        for (int cc = 0; cc < 2; ++cc) {                                  \
            const int ch = (ST) * 4 + lh * 2 + cc;                        \
            const float* pA = inb + ((ch >> 5) * CIN + (ch & 31)) * HWSZ; \
            if (mv) { av[cc*4+0] = pA[0];  av[cc*4+1] = pA[1];            \
                      av[cc*4+2] = pA[14]; av[cc*4+3] = pA[15]; }         \
            else    { av[cc*4+0]=av[cc*4+1]=av[cc*4+2]=av[cc*4+3]=0.f; }  \
        }                                                                 \
        const float4 v0 = *(const float4*)(w1p + (ST) * 16 + lh * 8);     \
        const float4 v1 = *(const float4*)(w1p + (ST) * 16 + lh * 8 + 4); \
        bv[0]=v0.x; bv[1]=v0.y; bv[2]=v0.z; bv[3]=v0.w;                   \
        bv[4]=v1.x; bv[5]=v1.y; bv[6]=v1.z; bv[7]=v1.w;                   \
    } while (0)

#define STORE_REGS(BUF) do {                                              \
        __half h[8], l[8];                                                \
        _Pragma("unroll")                                                 \
        for (int q = 0; q < 8; ++q) split2(av[q], h[q], l[q]);            \
        asm volatile("st.shared.v4.b32 [%0], {%1,%2,%3,%4};" ::           \
            "r"(stAh + (BUF) * bufB),                                     \
            "r"(*(const uint32_t*)&h[0]), "r"(*(const uint32_t*)&h[2]),   \
            "r"(*(const uint32_t*)&h[4]), "r"(*(const uint32_t*)&h[6]));  \
        asm volatile("st.shared.v4.b32 [%0], {%1,%2,%3,%4};" ::           \
            "r"(stAl + (BUF) * bufB),                                     \
            "r"(*(const uint32_t*)&l[0]), "r"(*(const uint32_t*)&l[2]),   \
            "r"(*(const uint32_t*)&l[4]), "r"(*(const uint32_t*)&l[6]));  \
        _Pragma("unroll")                                                 \
        for (int q = 0; q < 8; ++q) split2(bv[q], h[q], l[q]);            \
        asm volatile("st.shared.v4.b32 [%0], {%1,%2,%3,%4};" ::           \
            "r"(stBh + (BUF) * bufB),                                     \
            "r"(*(const uint32_t*)&h[0]), "r"(*(const uint32_t*)&h[2]),   \
            "r"(*(const uint32_t*)&h[4]), "r"(*(const uint32_t*)&h[6]));  \
        asm volatile("st.shared.v4.b32 [%0], {%1,%2,%3,%4};" ::           \
            "r"(stBl + (BUF) * bufB),                                     \
            "r"(*(const uint32_t*)&l[0]), "r"(*(const uint32_t*)&l[2]),   \
            "r"(*(const uint32_t*)&l[4]), "r"(*(const uint32_t*)&l[6]));  \
    } while (0)

    LOAD_REGS(0);
    STORE_REGS(0);
    __syncthreads();

    for (int st = 0; st < 64; ++st) {
        const int cur = st & 1;
        if (st + 1 < 64) LOAD_REGS(st + 1);

        uint32_t ah[2][4], al[2][4];
#pragma unroll
        for (int i = 0; i < 2; i++) {
            const uint32_t ro = (uint32_t)((am + i * 16 + aRow) * ASTR) * 2u + aByte;
            ldsm4(ah[i], baseAh + cur * bufB + ro);
            ldsm4(al[i], baseAl + cur * bufB + ro);
        }

#pragma unroll
        for (int jj = 0; jj < 4; ++jj) {
            const uint32_t ro = (uint32_t)((bn + jj * 16 + bRow) * ASTR) * 2u + bByte;
            uint32_t bh[4], bl[4];
            ldsm4(bh, baseBh + cur * bufB + ro);
            ldsm4(bl, baseBl + cur * bufB + ro);
#pragma unroll
            for (int t = 0; t < 2; ++t) {
                const int j = jj * 2 + t;
#pragma unroll
                for (int i = 0; i < 2; ++i) {
                    mma_f16(acc[i][j], ah[i], bh[t * 2], bh[t * 2 + 1]);  // hh
                    mma_f16(acc[i][j], ah[i], bl[t * 2], bl[t * 2 + 1]);  // hl
                    mma_f16(acc[i][j], al[i], bh[t * 2], bh[t * 2 + 1]);  // lh
                }
            }
        }

        if (st + 1 < 64) STORE_REGS(cur ^ 1);
        __syncthreads();
    }

    // ---- fused epilogue: bias + relu + window sums -> g_awin atomics
    const int qr = lane >> 2;   // 0..7
    const int qc = lane & 3;    // 0..3
    const int b0 = (mt * 128) / 169;
#pragma unroll
    for (int j = 0; j < 8; j++) {
        const int nbase = nt * 128 + bn + j * 8 + qc * 2;
        const float bia0 = __ldg(b1 + nbase);
        const float bia1 = __ldg(b1 + nbase + 1);
#pragma unroll
        for (int z = 0; z < 2; z++) {
            const float bia = z ? bia1 : bia0;
            float w4[2][4] = {{0.f,0.f,0.f,0.f},{0.f,0.f,0.f,0.f}};
#pragma unroll
            for (int i = 0; i < 2; i++) {
#pragma unroll
                for (int h = 0; h < 2; h++) {
                    const int mr = mt * 128 + am + i * 16 + qr + h * 8;
                    if (mr < M1) {
                        float v = acc[i][j][h * 2 + z] + bia;
                        v = v > 0.f ? v : 0.f;
                        const int bl2 = mr / 169 - b0;
                        const int pp  = mr % 169;
                        const int y   = pp / 13, x = pp - y * 13;
                        if (y < 12) { if (x < 12) w4[bl2][0] += v; if (x > 0) w4[bl2][1] += v; }
                        if (y > 0)  { if (x < 12) w4[bl2][2] += v; if (x > 0) w4[bl2][3] += v; }
                    }
                }
            }
            // butterfly over qr (lane bits 2..4) -> sums over the warp's 32 m-rows
#pragma unroll
            for (int o = 4; o <= 16; o <<= 1)
#pragma unroll
                for (int bl2 = 0; bl2 < 2; bl2++)
#pragma unroll
                    for (int t = 0; t < 4; t++)
                        w4[bl2][t] += __shfl_xor_sync(0xffffffffu, w4[bl2][t], o);
            if (qr == 0) {
                const int n = nbase + z;
#pragma unroll
                for (int bl2 = 0; bl2 < 2; bl2++) {
                    const int bg = b0 + bl2;
#pragma unroll
                    for (int t = 0; t < 4; t++)
                        if (w4[bl2][t] != 0.f)
                            atomicAdd(&g_awin[bg * 2048 + n * 4 + t], w4[bl2][t]);
                }
            }
        }
    }
#undef LOAD_REGS
#undef STORE_REGS
}

// =====================================================================
// Zero kernels (also align ncu capture slot: conv1 = launch index 3)
// =====================================================================
__global__ void k_z1() { g_awin[blockIdx.x * 256 + threadIdx.x] = 0.f; }
__global__ void k_z2() { g_awin[65536 + blockIdx.x * 256 + threadIdx.x] = 0.f; }
__global__ void k_z3() { g_att_acc[blockIdx.x * 256 + threadIdx.x] = 0.f; }

// =====================================================================
// Kernel 3: conv2-as-GEMM on window sums. M=64, N=512, K=2048.
// =====================================================================
__global__ __launch_bounds__(256)
void k_gemm2(const float* __restrict__ w2)
{
    __shared__ __align__(16) float As[16][64];
    __shared__ __align__(16) float Bs[16][64];

    const int ot = blockIdx.x, ks = blockIdx.y;
    const int tid = threadIdx.x;
    const int l = tid & 63, kg = tid >> 6;
    const int tm = tid >> 4, tn = tid & 15;

    float acc[4][4];
#pragma unroll
    for (int i = 0; i < 4; i++)
#pragma unroll
        for (int j = 0; j < 4; j++) acc[i][j] = 0.f;

    for (int it = 0; it < 8; ++it) {
        const int kb = ks * 128 + it * 16;
        const float4 av = *(const float4*)&g_awin[l * 2048 + kb + kg * 4];
        const float4 bv = *(const float4*)(w2 + (size_t)(ot * 64 + l) * 2048 + kb + kg * 4);
        As[kg * 4 + 0][l] = av.x; As[kg * 4 + 1][l] = av.y;
        As[kg * 4 + 2][l] = av.z; As[kg * 4 + 3][l] = av.w;
        Bs[kg * 4 + 0][l] = bv.x; Bs[kg * 4 + 1][l] = bv.y;
        Bs[kg * 4 + 2][l] = bv.z; Bs[kg * 4 + 3][l] = bv.w;
        __syncthreads();
#pragma unroll
        for (int kk = 0; kk < 16; ++kk) {
            float a[4], bbx[4];
            *(float4*)&a[0]   = *(const float4*)&As[kk][tm * 4];
            *(float4*)&bbx[0] = *(const float4*)&Bs[kk][tn * 4];
#pragma unroll
            for (int i = 0; i < 4; i++)
#pragma unroll
                for (int j = 0; j < 4; j++)
                    acc[i][j] = fmaf(a[i], bbx[j], acc[i][j]);
        }
        __syncthreads();
    }
#pragma unroll
    for (int i = 0; i < 4; i++)
#pragma unroll
        for (int j = 0; j < 4; j++)
            atomicAdd(&g_att_acc[(tm * 4 + i) * 512 + ot * 64 + tn * 4 + j], acc[i][j]);
}

// =====================================================================
// Kernel 4: sigmoid attention + argmax.
// =====================================================================
__global__ void k_att(const float* __restrict__ b2)
{
    const int b = blockIdx.x, r = threadIdx.x;
    float best = -1e30f; int bi = 0;
#pragma unroll
    for (int s = 0; s < 8; s++) {
        const float v = g_att_acc[b * 512 + s * 64 + r] * (1.f / 144.f) + b2[s * 64 + r];
        const float a = 1.f / (1.f + expf(-v));
        g_att[b * 512 + s * 64 + r] = a;
        if (a > best) { best = a; bi = s; }
    }
    g_maxidx[b * 64 + r] = bi;
}

// =====================================================================
// Kernel 5: grouped rank projection on tensor cores (fp16 3-pass).
//   Per CTA (q,s,b): C[hw 64][r 64] = x[b,s]^T . (w[s]*att)^T, K=256.
//   hw tiles at bases {0,48,96,144} overlap; duplicates write identical
//   values. Output xr stored [b][r][s][hw]; no atomics anywhere.
// =====================================================================
#define RK_ASTR 72                 // A row halves (64 m + 8 pad)
#define RK_BSTR 40                 // B row halves (32 k + 8 pad)
#define RK_APL  (32 * RK_ASTR)     // halves per A plane
#define RK_BPL  (64 * RK_BSTR)

__global__ __launch_bounds__(256)
void k_rank(const float* __restrict__ in, const float* __restrict__ rank_w,
            const float* __restrict__ rank_b)
{
    __shared__ __align__(16) __half sAh[2][RK_APL], sAl[2][RK_APL];
    __shared__ __align__(16) __half sBh[2][RK_BPL], sBl[2][RK_BPL];

    const int q = blockIdx.x;    // 0..3
    const int s = blockIdx.y;    // 0..7
    const int b = blockIdx.z;    // 0..63
    const int tid = threadIdx.x;
    const int hwb = q * 48;

    const float* img = in + (size_t)(b * 8 + s) * CIN * HWSZ;

    // ---- loader indices
    const int acr = tid >> 3;            // A k-row 0..31
    const int acg = (tid & 7) * 8;       // A hw-col base
    const int brr = tid >> 2;            // B r-row 0..63
    const int bcg = (tid & 3) * 8;       // B c-col base
    const float attB = g_att[b * 512 + s * 64 + brr];
    const float* wrow = rank_w + (size_t)(s * 64 + brr) * 256 + bcg;

    const uint32_t stA_h = smem_u32(&sAh[0][acr * RK_ASTR + acg]);
    const uint32_t stA_l = smem_u32(&sAl[0][acr * RK_ASTR + acg]);
    const uint32_t stB_h = smem_u32(&sBh[0][brr * RK_BSTR + bcg]);
    const uint32_t stB_l = smem_u32(&sBl[0][brr * RK_BSTR + bcg]);
    const uint32_t aplB = RK_APL * 2;    // bytes per A plane
    const uint32_t bplB = RK_BPL * 2;

    // ---- mma indices
    const int w    = tid >> 5;
    const int lane = tid & 31;
    const int wm   = w & 3;              // m16 tile
    const int wn   = w >> 2;             // n32 half
    const int lr   = lane & 7;
    const int sel  = lane >> 3;

    // A fragment via ldsm.trans from [k][m] smem
    const uint32_t aOff = (uint32_t)((((sel >> 1) * 8 + lr) * RK_ASTR
                                     + wm * 16 + (sel & 1) * 8)) * 2u;
    // B fragment (non-trans) from [r][c] smem
    const uint32_t bOff = (uint32_t)((wn * 32 + (sel >> 1) * 8 + lr) * RK_BSTR) * 2u
                          + (sel & 1) * 16;

    const uint32_t baseAh = smem_u32(&sAh[0][0]);
    const uint32_t baseAl = smem_u32(&sAl[0][0]);
    const uint32_t baseBh = smem_u32(&sBh[0][0]);
    const uint32_t baseBl = smem_u32(&sBl[0][0]);

    float acc[4][4];
#pragma unroll
    for (int j = 0; j < 4; j++)
#pragma unroll
        for (int c = 0; c < 4; c++) acc[j][c] = 0.f;

    float avv[8], bvv[8];

#define RK_LOAD(ST) do {                                                    \
        const float* ar = img + (size_t)((ST) * 32 + acr) * HWSZ + hwb + acg;\
        const int hw0 = hwb + acg;                                          \
        if (hw0 + 7 < HWSZ) {                                               \
            const float4 t0 = *(const float4*)ar;                           \
            const float4 t1 = *(const float4*)(ar + 4);                     \
            avv[0]=t0.x; avv[1]=t0.y; avv[2]=t0.z; avv[3]=t0.w;             \
            avv[4]=t1.x; avv[5]=t1.y; avv[6]=t1.z; avv[7]=t1.w;             \
        } else {                                                            \
            _Pragma("unroll")                                               \
            for (int k2 = 0; k2 < 8; ++k2)                                  \
                avv[k2] = (hw0 + k2 < HWSZ) ? ar[k2] : 0.f;                 \
        }                                                                   \
        const float4 u0 = *(const float4*)(wrow + (ST) * 32);               \
        const float4 u1 = *(const float4*)(wrow + (ST) * 32 + 4);           \
        bvv[0]=u0.x*attB; bvv[1]=u0.y*attB; bvv[2]=u0.z*attB;               \
        bvv[3]=u0.w*attB; bvv[4]=u1.x*attB; bvv[5]=u1.y*attB;               \
        bvv[6]=u1.z*attB; bvv[7]=u1.w*attB;                                 \
    } while (0)

#define RK_STORE(BUF) do {                                                  \
        __half h[8], l[8];                                                  \
        _Pragma("unroll")                                                   \
        for (int k2 = 0; k2 < 8; ++k2) split2(avv[k2], h[k2], l[k2]);       \
        asm volatile("st.shared.v4.b32 [%0], {%1,%2,%3,%4};" ::             \
            "r"(stA_h + (BUF) * aplB),                                      \
            "r"(*(const uint32_t*)&h[0]), "r"(*(const uint32_t*)&h[2]),     \
            "r"(*(const uint32_t*)&h[4]), "r"(*(const uint32_t*)&h[6]));    \
        asm volatile("st.shared.v4.b32 [%0], {%1,%2,%3,%4};" ::             \
            "r"(stA_l + (BUF) * aplB),                                      \
            "r"(*(const uint32_t*)&l[0]), "r"(*(const uint32_t*)&l[2]),     \
            "r"(*(const uint32_t*)&l[4]), "r"(*(const uint32_t*)&l[6]));    \
        _Pragma("unroll")                                                   \
        for (int k2 = 0; k2 < 8; ++k2) split2(bvv[k2], h[k2], l[k2]);       \
        asm volatile("st.shared.v4.b32 [%0], {%1,%2,%3,%4};" ::             \
            "r"(stB_h + (BUF) * bplB),                                      \
            "r"(*(const uint32_t*)&h[0]), "r"(*(const uint32_t*)&h[2]),     \
            "r"(*(const uint32_t*)&h[4]), "r"(*(const uint32_t*)&h[6]));    \
        asm volatile("st.shared.v4.b32 [%0], {%1,%2,%3,%4};" ::             \
            "r"(stB_l + (BUF) * bplB),                                      \
            "r"(*(const uint32_t*)&l[0]), "r"(*(const uint32_t*)&l[2]),     \
            "r"(*(const uint32_t*)&l[4]), "r"(*(const uint32_t*)&l[6]));    \
    } while (0)

    RK_LOAD(0);
    RK_STORE(0);
    __syncthreads();

    for (int st = 0; st < 8; ++st) {
        const int cur = st & 1;
        if (st + 1 < 8) RK_LOAD(st + 1);

#pragma unroll
        for (int ks = 0; ks < 2; ++ks) {
            uint32_t ah[4], al[4];
            const uint32_t ao = cur * aplB + (uint32_t)(ks * 16 * RK_ASTR) * 2u + aOff;
            ldsm4t(ah, baseAh + ao);
            ldsm4t(al, baseAl + ao);
#pragma unroll
            for (int jj = 0; jj < 2; ++jj) {
                uint32_t bh[4], bl2[4];
                const uint32_t bo = cur * bplB + (uint32_t)(jj * 16 * RK_BSTR) * 2u
                                    + ks * 32 + bOff;
                ldsm4(bh, baseBh + bo);
                ldsm4(bl2, baseBl + bo);
#pragma unroll
                for (int t = 0; t < 2; ++t) {
                    const int jn = jj * 2 + t;
                    mma_f16(acc[jn], ah, bh[t * 2], bh[t * 2 + 1]);   // hh
                    mma_f16(acc[jn], ah, bl2[t * 2], bl2[t * 2 + 1]); // hl
                    mma_f16(acc[jn], al, bh[t * 2], bh[t * 2 + 1]);   // lh
                }
            }
        }

        if (st + 1 < 8) RK_STORE(cur ^ 1);
        __syncthreads();
    }

    // ---- epilogue: + rank_b*att, store xr[b][r][s][hw]
    const int g  = lane >> 2;
    const int tg = lane & 3;
#pragma unroll
    for (int j = 0; j < 4; j++) {
        const int r0 = wn * 32 + j * 8 + tg * 2;
        const float at0 = g_att[b * 512 + s * 64 + r0];
        const float at1 = g_att[b * 512 + s * 64 + r0 + 1];
        const float rb0 = rank_b[s * 64 + r0] * at0;
        const float rb1 = rank_b[s * 64 + r0 + 1] * at1;
#pragma unroll
        for (int h = 0; h < 2; h++) {
            const int hw = hwb + wm * 16 + g + h * 8;
            if (hw < HWSZ) {
                g_xr[((size_t)(b * 64 + r0) * 8 + s) * HWSZ + hw]     = acc[j][h * 2 + 0] + rb0;
                g_xr[((size_t)(b * 64 + r0 + 1) * 8 + s) * HWSZ + hw] = acc[j][h * 2 + 1] + rb1;
            }
        }
    }
#undef RK_LOAD
#undef RK_STORE
}

// =====================================================================
// Kernel 6: y[b,r] = sum_hw piv*(tot-piv)/(7*196), then final linear.
// =====================================================================
__global__ __launch_bounds__(256)
void k_final(const float* __restrict__ lin_w, const float* __restrict__ lin_b,
             float* __restrict__ out)
{
    __shared__ float pooled[64];
    const int b = blockIdx.x;
    const int tid = threadIdx.x, wid = tid >> 5, lane = tid & 31;

#pragma unroll
    for (int rr = 0; rr < 8; ++rr) {
        const int r = wid * 8 + rr;
        const int mi = g_maxidx[b * 64 + r];
        const float* base = g_xr + (size_t)(b * 64 + r) * 8 * HWSZ;
        float sum = 0.f;
        for (int hw = lane; hw < HWSZ; hw += 32) {
            float tot = 0.f, piv = 0.f;
#pragma unroll
            for (int s = 0; s < 8; s++) {
                const float v = base[s * HWSZ + hw];
                tot += v;
                if (s == mi) piv = v;
            }
            sum += piv * (tot - piv);
        }
#pragma unroll
        for (int o = 16; o; o >>= 1) sum += __shfl_down_sync(0xffffffffu, sum, o);
        if (lane == 0) pooled[r] = sum * (1.f / (7.f * 196.f));
    }
    __syncthreads();

#pragma unroll
    for (int oo = 0; oo < 2; ++oo) {
        const int o = oo * 256 + tid;
        float a = lin_b[o];
#pragma unroll
        for (int r = 0; r < 64; r++)
            a = fmaf(pooled[r], lin_w[o * 64 + r], a);
        out[b * 512 + o] = a;
    }
}

// =====================================================================
extern "C" void kernel_launch(void* const* d_in, const int* in_sizes, int n_in,
                              void* d_out, int out_size)
{
    const float* in = (const float*)d_in[0];
    const float* w1 = (const float*)d_in[1];
    const float* b1 = (const float*)d_in[2];
    const float* w2 = (const float*)d_in[3];
    const float* b2 = (const float*)d_in[4];
    const float* rw = (const float*)d_in[5];
    const float* rb = (const float*)d_in[6];
    const float* lw = (const float*)d_in[7];
    const float* lb = (const float*)d_in[8];
    float* out = (float*)d_out;

    k_z1<<<256, 256>>>();
    k_z2<<<256, 256>>>();
    k_z3<<<128, 256>>>();
    k_conv1<<<dim3(85, 4), 256>>>(in, w1, b1);   // ncu capture slot (index 3)
    k_gemm2<<<dim3(8, 16), 256>>>(w2);
    k_att  <<<64, 64>>>(b2);
    k_rank <<<dim3(4, 8, 64), 256>>>(in, rw, rb);
    k_final<<<64, 256>>>(lw, lb, out);
}